// round 13
// baseline (speedup 1.0000x reference)
#include <cuda_runtime.h>
#include <cuda_fp16.h>

// B=512 rows, L=16 labels, N=8192 values. Single kernel, 512 blocks.
// loss = sum_l inv[l] * A_l,  inv[l] = 1/((np*nn)^2 * 256)
// A_l  = sum_{i pos, j neg} S[i,j],  S[i,j] = sum_{c,d} relu(1 - x[i,c] + x[j,d])
// Hot loop: HFMA2.RELU + HADD2, 1 fma-pipe instr per element pair.
// Each block: ONE j-tile (16 rows, xq kept in registers) x TWO i-tiles (32 rows).
// Skeletal epilogue (S stored once per tile; label sums reconstructed from masks),
// fixed-point atomic accumulation into g_acc[16]; ticketed last block combines.

#define NROW 512
#define NL   16
#define TI   16
#define NBLK 512                 // 32 j-tiles x 16 i-tile-pairs
#define XP   20                  // padded row stride (floats) for xi tiles
#define FPSCALE    67108864.0f   // 2^26
#define FPSCALE_I  (1.0f / 67108864.0f)

__device__ float              g_inv[NL];
__device__ unsigned long long g_acc[NL];     // zero-initialized at load
__device__ unsigned int       g_cnt = 0;

__global__ void __launch_bounds__(256, 6) k_all(const int* __restrict__ yt,
                                                const float* __restrict__ yp,
                                                float* __restrict__ out, int n_out) {
    __shared__ __align__(16) float   xi[2 * TI * XP];  // two i-tiles fp32, padded rows
    __shared__ __align__(16) __half2 xjh2[TI * TI];    // j-tile, splatted half2 [row][d]
    __shared__ float    Ss[2 * 256];                   // per-thread S, tile 0 and 1
    __shared__ float    A2[NL * 17];                   // stage-2 partials [l][ic]
    __shared__ float    wfin[NL];
    __shared__ unsigned pmI[2 * TI], nmJ[TI];
    __shared__ int      cnt_s[NL];
    __shared__ int      is_last;

    const int b   = blockIdx.x;
    const int bj  = b & 31;          // j-tile (0..31)
    const int bp  = b >> 5;          // i-tile pair (0..15): rows bp*32..bp*32+31
    const int tid = threadIdx.x;

    // ---- stage tiles ------------------------------------------------------------
    {
        int r = tid >> 4, c = tid & 15;
        xi[r * XP + c]        = yp[bp * 512 + tid];          // i-rows 0..15
        xi[(16 + r) * XP + c] = yp[bp * 512 + 256 + tid];    // i-rows 16..31
        xjh2[r * TI + c] = __float2half2_rn(yp[bj * 256 + r * TI + c]);
    }

    // ---- block 0: per-label n_pos -> g_inv ----------------------------------------
    if (b == 0) {
        if (tid < NL) cnt_s[tid] = 0;
        __syncthreads();
        const int r0 = 2 * tid;
        unsigned m0 = 0, m1 = 0;
        const int4* y4 = (const int4*)(yt + r0 * NL);
        #pragma unroll
        for (int q = 0; q < 4; q++) {
            int4 v = y4[q];
            if (v.x) m0 |= 1u << (4 * q + 0);
            if (v.y) m0 |= 1u << (4 * q + 1);
            if (v.z) m0 |= 1u << (4 * q + 2);
            if (v.w) m0 |= 1u << (4 * q + 3);
        }
        #pragma unroll
        for (int q = 0; q < 4; q++) {
            int4 v = y4[4 + q];
            if (v.x) m1 |= 1u << (4 * q + 0);
            if (v.y) m1 |= 1u << (4 * q + 1);
            if (v.z) m1 |= 1u << (4 * q + 2);
            if (v.w) m1 |= 1u << (4 * q + 3);
        }
        #pragma unroll
        for (int l = 0; l < NL; l++) {
            unsigned b0 = __ballot_sync(0xffffffffu, (m0 >> l) & 1u);
            unsigned b1 = __ballot_sync(0xffffffffu, (m1 >> l) & 1u);
            if ((tid & 31) == 0) atomicAdd(&cnt_s[l], __popc(b0) + __popc(b1));
        }
        __syncthreads();
        if (tid < NL) {
            int np = cnt_s[tid], nn = NROW - np;
            float d = (float)np * (float)nn;            // <= 2^18, exact in fp32
            g_inv[tid] = (np > 0 && nn > 0) ? 1.0f / (d * d * 256.0f) : 0.0f;
            // published by the same threads' __threadfence in the epilogue
        }
    }

    // ---- row masks: 32 i-rows + 16 j-rows -------------------------------------------
    if (tid < 3 * TI) {
        int row = (tid < 2 * TI) ? (bp * 32 + tid) : (bj * TI + (tid - 2 * TI));
        unsigned m = 0;
        const int4* y4 = (const int4*)(yt + row * NL);
        #pragma unroll
        for (int q = 0; q < 4; q++) {
            int4 v = y4[q];
            if (v.x) m |= 1u << (4 * q + 0);
            if (v.y) m |= 1u << (4 * q + 1);
            if (v.z) m |= 1u << (4 * q + 2);
            if (v.w) m |= 1u << (4 * q + 3);
        }
        if (tid < 2 * TI) pmI[tid] = m;
        else              nmJ[tid - 2 * TI] = (~m) & 0xFFFFu;
    }
    __syncthreads();

    // ---- hot loops: one j-register-set, two i-tiles -----------------------------------
    const int il = tid >> 4;
    const int jl = tid & 15;
    const __half2 one2 = __float2half2_rn(1.0f);
    const __half2 hz   = __float2half2_rn(0.0f);

    // j-row values, register-resident across both tiles (16 splatted half2)
    uint4 q0, q1, q2, q3;
    {
        const uint4* qp = (const uint4*)&xjh2[jl * TI];
        q0 = qp[0]; q1 = qp[1]; q2 = qp[2]; q3 = qp[3];
    }
    unsigned qw[16] = {q0.x, q0.y, q0.z, q0.w,  q1.x, q1.y, q1.z, q1.w,
                       q2.x, q2.y, q2.z, q2.w,  q3.x, q3.y, q3.z, q3.w};

    #pragma unroll
    for (int t = 0; t < 2; t++) {
        __half2 ah[8];
        {
            const float4* xr = (const float4*)&xi[(t * TI + il) * XP];
            float4 a = xr[0], c4 = xr[1], d4 = xr[2], e4 = xr[3];
            ah[0] = __floats2half2_rn(1.0f - a.x,  1.0f - a.y);
            ah[1] = __floats2half2_rn(1.0f - a.z,  1.0f - a.w);
            ah[2] = __floats2half2_rn(1.0f - c4.x, 1.0f - c4.y);
            ah[3] = __floats2half2_rn(1.0f - c4.z, 1.0f - c4.w);
            ah[4] = __floats2half2_rn(1.0f - d4.x, 1.0f - d4.y);
            ah[5] = __floats2half2_rn(1.0f - d4.z, 1.0f - d4.w);
            ah[6] = __floats2half2_rn(1.0f - e4.x, 1.0f - e4.y);
            ah[7] = __floats2half2_rn(1.0f - e4.z, 1.0f - e4.w);
        }

        __half2 acc[8];
        #pragma unroll
        for (int k = 0; k < 8; k++) acc[k] = hz;

        #pragma unroll
        for (int d = 0; d < 16; d++) {
            __half2 xq = *reinterpret_cast<__half2*>(&qw[d]);
            #pragma unroll
            for (int k = 0; k < 8; k++) {
                __half2 r = __hfma2_relu(ah[k], one2, xq);   // relu(ah + xq)
                acc[k] = __hadd2(acc[k], r);
            }
        }

        acc[0] = __hadd2(acc[0], acc[1]);
        acc[2] = __hadd2(acc[2], acc[3]);
        acc[4] = __hadd2(acc[4], acc[5]);
        acc[6] = __hadd2(acc[6], acc[7]);
        acc[0] = __hadd2(acc[0], acc[2]);
        acc[4] = __hadd2(acc[4], acc[6]);
        acc[0] = __hadd2(acc[0], acc[4]);
        float2 fS = __half22float2(acc[0]);
        Ss[t * 256 + tid] = fS.x + fS.y;
    }
    __syncthreads();

    // ---- skeletal epilogue: reconstruct label sums from masks --------------------------
    {
        const int l = tid & 15, ic = tid >> 4;
        float a = 0.0f;
        if ((pmI[ic] >> l) & 1u) {
            #pragma unroll
            for (int j = 0; j < TI; j++)
                a += ((nmJ[j] >> l) & 1u) ? Ss[ic * TI + j] : 0.0f;
        }
        if ((pmI[16 + ic] >> l) & 1u) {
            #pragma unroll
            for (int j = 0; j < TI; j++)
                a += ((nmJ[j] >> l) & 1u) ? Ss[256 + ic * TI + j] : 0.0f;
        }
        A2[l * 17 + ic] = a;
    }
    __syncthreads();

    if (tid < NL) {
        float s = 0.0f;
        #pragma unroll
        for (int c = 0; c < 16; c++) s += A2[tid * 17 + c];
        // deterministic fixed-point accumulation (A_l >= 0 always)
        atomicAdd(&g_acc[tid], (unsigned long long)__float2ll_rn(s * FPSCALE));
        __threadfence();            // also publishes block 0's g_inv writes
    }
    __syncthreads();

    if (tid == 0) {
        unsigned t = atomicAdd(&g_cnt, 1u);
        is_last = (t == NBLK - 1);
    }
    __syncthreads();

    // ---- last block: tiny tail ------------------------------------------------------------
    if (is_last) {
        __threadfence();
        if (tid < NL) {
            long long v = (long long)g_acc[tid];
            wfin[tid] = (float)v * FPSCALE_I * g_inv[tid];
            g_acc[tid] = 0ULL;      // reset for next graph replay
        }
        __syncthreads();
        if (tid == 0) {
            float loss = 0.0f;
            #pragma unroll
            for (int l2 = 0; l2 < NL; l2++) loss += wfin[l2];
            out[0] = loss;
            g_cnt  = 0;             // reset for next graph replay
        }
        for (int i = tid + 1; i < n_out; i += 256) out[i] = 0.0f;
    }
}

extern "C" void kernel_launch(void* const* d_in, const int* in_sizes, int n_in,
                              void* d_out, int out_size) {
    const int*   yt  = (const int*)d_in[0];    // y_true int32 [512*16]
    const float* yp  = (const float*)d_in[1];  // y_pred fp32  [512*16]
    float*       out = (float*)d_out;

    k_all<<<NBLK, 256>>>(yt, yp, out, out_size);
}

// round 14
// speedup vs baseline: 1.1275x; 1.1275x over previous
#include <cuda_runtime.h>
#include <cuda_fp16.h>

// B=512 rows, L=16 labels, N=8192 values. Single kernel, 1024 blocks.
// loss = sum_l inv[l] * A_l,  inv[l] = 1/((np*nn)^2 * 256)
// A_l  = sum_{i pos, j neg} S[i,j],  S[i,j] = sum_{c,d} relu(1 - x[i,c] + x[j,d])
// Hot loop: HFMA2.RELU + HADD2 (1 fma-pipe instr per element pair).
// Skeletal epilogue: S stored once per thread; per-label sums reconstructed
// from row masks in stage 2. Per-label partials -> g_acc[16] in 2^26 fixed
// point (deterministic); ticketed last block combines.

#define NROW 512
#define NL   16
#define TI   16
#define GB   32
#define NBLK 1024
#define XP   20                  // padded row stride (floats) for xi tile
#define FPSCALE    67108864.0f   // 2^26
#define FPSCALE_I  (1.0f / 67108864.0f)

__device__ float              g_inv[NL];
__device__ unsigned long long g_acc[NL];     // zero-initialized at load
__device__ unsigned int       g_cnt = 0;

__global__ void __launch_bounds__(256, 6) k_all(const int* __restrict__ yt,
                                                const float* __restrict__ yp,
                                                float* __restrict__ out, int n_out) {
    __shared__ __align__(16) float   xi[TI * XP];      // i-tile fp32, padded rows
    __shared__ __align__(16) __half2 xjh2[TI * TI];    // j-tile, splatted half2 [row][d]
    __shared__ float    Ss[256];                       // per-thread S
    __shared__ float    A2[NL * 17];                   // stage-2 partials [l][ic]
    __shared__ float    wfin[NL];
    __shared__ unsigned pmI[TI], nmJ[TI];
    __shared__ int      cnt_s[NL];
    __shared__ int      is_last;

    const int b   = blockIdx.x;
    const int bi  = b & (GB - 1);
    const int bj  = b >> 5;
    const int tid = threadIdx.x;

    // ---- stage tiles ------------------------------------------------------------
    {
        int r = tid >> 4, c = tid & 15;
        xi[r * XP + c] = yp[bi * 256 + tid];
        // j value splatted into both halves: xjh2[row][d] = (h, h)
        xjh2[r * TI + c] = __float2half2_rn(yp[bj * 256 + r * TI + c]);
    }

    // ---- block 0: per-label n_pos -> g_inv ----------------------------------------
    if (b == 0) {
        if (tid < NL) cnt_s[tid] = 0;
        __syncthreads();
        const int r0 = 2 * tid;
        unsigned m0 = 0, m1 = 0;
        const int4* y4 = (const int4*)(yt + r0 * NL);
        #pragma unroll
        for (int q = 0; q < 4; q++) {
            int4 v = y4[q];
            if (v.x) m0 |= 1u << (4 * q + 0);
            if (v.y) m0 |= 1u << (4 * q + 1);
            if (v.z) m0 |= 1u << (4 * q + 2);
            if (v.w) m0 |= 1u << (4 * q + 3);
        }
        #pragma unroll
        for (int q = 0; q < 4; q++) {
            int4 v = y4[4 + q];
            if (v.x) m1 |= 1u << (4 * q + 0);
            if (v.y) m1 |= 1u << (4 * q + 1);
            if (v.z) m1 |= 1u << (4 * q + 2);
            if (v.w) m1 |= 1u << (4 * q + 3);
        }
        #pragma unroll
        for (int l = 0; l < NL; l++) {
            unsigned b0 = __ballot_sync(0xffffffffu, (m0 >> l) & 1u);
            unsigned b1 = __ballot_sync(0xffffffffu, (m1 >> l) & 1u);
            if ((tid & 31) == 0) atomicAdd(&cnt_s[l], __popc(b0) + __popc(b1));
        }
        __syncthreads();
        if (tid < NL) {
            int np = cnt_s[tid], nn = NROW - np;
            float d = (float)np * (float)nn;            // <= 2^18, exact in fp32
            g_inv[tid] = (np > 0 && nn > 0) ? 1.0f / (d * d * 256.0f) : 0.0f;
            // published by the same threads' __threadfence in the epilogue
        }
    }

    // ---- row masks: 16 i-rows + 16 j-rows -------------------------------------------
    if (tid < 2 * TI) {
        int row = (tid < TI) ? (bi * TI + tid) : (bj * TI + (tid - TI));
        unsigned m = 0;
        const int4* y4 = (const int4*)(yt + row * NL);
        #pragma unroll
        for (int q = 0; q < 4; q++) {
            int4 v = y4[q];
            if (v.x) m |= 1u << (4 * q + 0);
            if (v.y) m |= 1u << (4 * q + 1);
            if (v.z) m |= 1u << (4 * q + 2);
            if (v.w) m |= 1u << (4 * q + 3);
        }
        if (tid < TI) pmI[tid] = m;
        else          nmJ[tid - TI] = (~m) & 0xFFFFu;
    }
    __syncthreads();

    // ---- hot loop --------------------------------------------------------------------
    const int il = tid >> 4;
    const int jl = tid & 15;

    // a_c = 1 - x[i,c], packed as 8 half2
    __half2 ah[8];
    {
        const float4* xr = (const float4*)&xi[il * XP];
        float4 a = xr[0], c4 = xr[1], d4 = xr[2], e4 = xr[3];
        ah[0] = __floats2half2_rn(1.0f - a.x,  1.0f - a.y);
        ah[1] = __floats2half2_rn(1.0f - a.z,  1.0f - a.w);
        ah[2] = __floats2half2_rn(1.0f - c4.x, 1.0f - c4.y);
        ah[3] = __floats2half2_rn(1.0f - c4.z, 1.0f - c4.w);
        ah[4] = __floats2half2_rn(1.0f - d4.x, 1.0f - d4.y);
        ah[5] = __floats2half2_rn(1.0f - d4.z, 1.0f - d4.w);
        ah[6] = __floats2half2_rn(1.0f - e4.x, 1.0f - e4.y);
        ah[7] = __floats2half2_rn(1.0f - e4.z, 1.0f - e4.w);
    }

    const __half2 one2 = __float2half2_rn(1.0f);
    const __half2 hz   = __float2half2_rn(0.0f);
    __half2 acc[8];
    #pragma unroll
    for (int k = 0; k < 8; k++) acc[k] = hz;

    const uint4* qp = (const uint4*)&xjh2[jl * TI];   // 16 half2 = 4x uint4
    #pragma unroll
    for (int dc = 0; dc < 4; dc++) {
        uint4 qv = qp[dc];                             // 4 splatted half2 (4 d's)
        unsigned qw[4] = {qv.x, qv.y, qv.z, qv.w};
        #pragma unroll
        for (int di = 0; di < 4; di++) {
            __half2 xq = *reinterpret_cast<__half2*>(&qw[di]);
            #pragma unroll
            for (int k = 0; k < 8; k++) {
                __half2 r = __hfma2_relu(ah[k], one2, xq);   // relu(ah + xq)
                acc[k] = __hadd2(acc[k], r);
            }
        }
    }

    // tree-reduce the 8 half2 accumulators (values ~330 << 65504: safe)
    acc[0] = __hadd2(acc[0], acc[1]);
    acc[2] = __hadd2(acc[2], acc[3]);
    acc[4] = __hadd2(acc[4], acc[5]);
    acc[6] = __hadd2(acc[6], acc[7]);
    acc[0] = __hadd2(acc[0], acc[2]);
    acc[4] = __hadd2(acc[4], acc[6]);
    acc[0] = __hadd2(acc[0], acc[4]);
    float2 fS = __half22float2(acc[0]);

    // ---- skeletal epilogue: store S once, reconstruct label sums from masks ----------
    Ss[tid] = fS.x + fS.y;
    __syncthreads();

    {
        const int l = tid & 15, ic = tid >> 4;
        float a = 0.0f;
        if ((pmI[ic] >> l) & 1u) {
            #pragma unroll
            for (int j = 0; j < TI; j++)
                a += ((nmJ[j] >> l) & 1u) ? Ss[ic * TI + j] : 0.0f;
        }
        A2[l * 17 + ic] = a;
    }
    __syncthreads();

    if (tid < NL) {
        float s = 0.0f;
        #pragma unroll
        for (int c = 0; c < 16; c++) s += A2[tid * 17 + c];
        // deterministic fixed-point accumulation (A_l >= 0 always)
        atomicAdd(&g_acc[tid], (unsigned long long)__float2ll_rn(s * FPSCALE));
        __threadfence();            // also publishes block 0's g_inv writes
    }
    __syncthreads();

    if (tid == 0) {
        unsigned t = atomicAdd(&g_cnt, 1u);
        is_last = (t == NBLK - 1);
    }
    __syncthreads();

    // ---- last block: tiny tail ------------------------------------------------------------
    if (is_last) {
        __threadfence();
        if (tid < NL) {
            long long v = (long long)g_acc[tid];
            wfin[tid] = (float)v * FPSCALE_I * g_inv[tid];
            g_acc[tid] = 0ULL;      // reset for next graph replay
        }
        __syncthreads();
        if (tid == 0) {
            float loss = 0.0f;
            #pragma unroll
            for (int l2 = 0; l2 < NL; l2++) loss += wfin[l2];
            out[0] = loss;
            g_cnt  = 0;             // reset for next graph replay
        }
        for (int i = tid + 1; i < n_out; i += 256) out[i] = 0.0f;
    }
}

extern "C" void kernel_launch(void* const* d_in, const int* in_sizes, int n_in,
                              void* d_out, int out_size) {
    const int*   yt  = (const int*)d_in[0];    // y_true int32 [512*16]
    const float* yp  = (const float*)d_in[1];  // y_pred fp32  [512*16]
    float*       out = (float*)d_out;

    k_all<<<NBLK, 256>>>(yt, yp, out, out_size);
}